// round 8
// baseline (speedup 1.0000x reference)
#include <cuda_runtime.h>

// CustomRouterRouter — reference-rounding-matched (Eigen/NEON gemv realization)
// + deep x-only register prefetch (W is L1-resident, loaded just-in-time).
//
// Numerics (LOCKED, rel_err 3.06e-5): per (row,e), 4 SIMD-lane fp32
// accumulators with fused FMA, lane j takes k ≡ j (mod 4), ascending packets;
// horizontal reduce in Eigen predux order (a0+a2)+(a1+a3); single-rounding
// epilogue (+b, den add, IEEE divide, mul-then-add).
//
// Perf: parallelism fixed at 16384 threads (grid-limited occupancy), so DRAM
// latency is covered by per-thread MLP on the x stream only. W (32 KB) is
// shared by all warps -> L1 hits; buffering it in registers caused spills
// (R7: regs=255, L1=59% local traffic). x buffer = 16 float4 = 64 regs.

#define FT 0.5f
#define PFD 16   // x prefetch depth in float4 packets

__global__ __launch_bounds__(64) void router_seq_kernel(
    const float4* __restrict__ x4,
    const float*  __restrict__ weights,
    const float4* __restrict__ W4,
    const float*  __restrict__ b,
    float*        __restrict__ out,
    int L, int Hv)
{
    const int t   = blockIdx.x * blockDim.x + threadIdx.x;
    const int row = t >> 1;
    const int e   = t & 1;
    if (row >= L) return;

    const float4* __restrict__ xr = x4 + (size_t)row * Hv;
    const float4* __restrict__ wr = W4 + (size_t)e * Hv;

    // 4 independent lane accumulators (NEON lanes), ascending packet order.
    float a0 = 0.f, a1 = 0.f, a2 = 0.f, a3 = 0.f;

    // Prime the x prefetch buffer with packets [0, PFD).
    float4 xb[PFD];
    #pragma unroll
    for (int j = 0; j < PFD; j++) xb[j] = xr[j];

    // Main loop: consume packet i+j, prefetch packet i+PFD+j.
    // W loaded just-in-time (L1 hit after first wave).
    #pragma unroll 1
    for (int i = 0; i < Hv - PFD; i += PFD) {
        #pragma unroll
        for (int j = 0; j < PFD; j++) {
            const float4 xv = xb[j];
            xb[j] = xr[i + PFD + j];
            const float4 wv = __ldg(&wr[i + j]);
            a0 = fmaf(xv.x, wv.x, a0);
            a1 = fmaf(xv.y, wv.y, a1);
            a2 = fmaf(xv.z, wv.z, a2);
            a3 = fmaf(xv.w, wv.w, a3);
        }
    }
    // Tail: consume the last PFD packets.
    #pragma unroll
    for (int j = 0; j < PFD; j++) {
        const float4 xv = xb[j];
        const float4 wv = __ldg(&wr[Hv - PFD + j]);
        a0 = fmaf(xv.x, wv.x, a0);
        a1 = fmaf(xv.y, wv.y, a1);
        a2 = fmaf(xv.z, wv.z, a2);
        a3 = fmaf(xv.w, wv.w, a3);
    }

    // Eigen NEON predux order: (a0+a2) + (a1+a3).
    const float acc = __fadd_rn(__fadd_rn(a0, a2), __fadd_rn(a1, a3));

    // lin_e = dot_e + b_e   (single rounding)
    const float lin = __fadd_rn(acc, __ldg(&b[e]));

    // den = lin0 + lin1 (single rounding). Partner thread is adjacent lane.
    const float other = __shfl_xor_sync(0xffffffffu, lin, 1);
    const float lin0  = (e == 0) ? lin : other;
    const float lin1  = (e == 0) ? other : lin;
    const float den   = __fadd_rn(lin0, lin1);

    // IEEE correctly-rounded fp32 division.
    const float l = __fdiv_rn(lin, den);

    // hs = weights[row // (L/2)][0]; weights is (2,2) row-major.
    const float hs = __ldg(&weights[(row >= (L >> 1)) ? 2 : 0]);

    float rr_self, rr2;
    if (hs >= FT) {
        rr2     = __fdiv_rn(__fsub_rn(1.0f, hs), 1.0f - FT);
        rr_self = (e == 0) ? __fdiv_rn(__fsub_rn(hs, FT), 1.0f - FT) : 0.0f;
    } else {
        rr2     = __fdiv_rn(hs, FT);
        rr_self = (e == 0) ? 0.0f : __fdiv_rn(__fsub_rn(FT, hs), FT);
    }

    // einsum epilogue: out = rr_self + round(rr2 * lin), mul then add.
    out[row * 2 + e] = __fadd_rn(rr_self, __fmul_rn(rr2, l));
}

extern "C" void kernel_launch(void* const* d_in, const int* in_sizes, int n_in,
                              void* d_out, int out_size) {
    const float* x       = (const float*)d_in[0];
    const float* weights = (const float*)d_in[1];
    const float* W       = (const float*)d_in[2];
    const float* b       = (const float*)d_in[3];
    float* out = (float*)d_out;

    const int E  = in_sizes[3];            // 2
    const int H  = in_sizes[2] / E;        // 4096
    const int L  = in_sizes[0] / H;        // 8192
    const int Hv = H / 4;                  // 1024

    const int total   = L * 2;             // one thread per (row, e)
    const int threads = 64;
    const int blocks  = (total + threads - 1) / threads;

    router_seq_kernel<<<blocks, threads>>>((const float4*)x, weights,
                                           (const float4*)W, b, out, L, Hv);
}

// round 9
// speedup vs baseline: 1.1751x; 1.1751x over previous
#include <cuda_runtime.h>

// CustomRouterRouter — reference-rounding-matched (Eigen/NEON gemv realization)
// + cp.async 4-stage smem pipeline for DRAM saturation.
//
// Numerics (LOCKED, rel_err 3.06e-5): per (row,e), 4 SIMD-lane fp32
// accumulators with fused FMA, lane j takes k ≡ j (mod 4), ascending packets;
// horizontal reduce in Eigen predux order (a0+a2)+(a1+a3); single-rounding
// epilogue (+b, den add, IEEE divide, mul-then-add).
//
// Perf: grid is pinned at 16384 chains (512 warps chip-wide), so HBM latency
// must be covered by async-copy depth, not registers (R7/R8: register
// prefetch spills, DRAM stuck at 22%). Each block stages x tiles
// (32 rows x 16 packets, 8 KB) via cp.async.cg with 3 stages in flight:
// 256 blocks x 24 KB = 6 MB in flight >> BW*latency (~2 MB).

#define FT   0.5f
#define PKT  16            // packets (float4) per stage per row
#define STG  4             // pipeline stages
#define RPB  32            // rows per block
#define THR  64            // threads per block (= 2 chains per row)

__device__ __forceinline__ void cp_async16(void* smem_dst, const void* gmem_src) {
    unsigned saddr = (unsigned)__cvta_generic_to_shared(smem_dst);
    asm volatile("cp.async.cg.shared.global [%0], [%1], 16;\n"
                 :: "r"(saddr), "l"(gmem_src));
}
__device__ __forceinline__ void cp_commit() {
    asm volatile("cp.async.commit_group;\n" ::: "memory");
}
__device__ __forceinline__ void cp_wait3() {
    asm volatile("cp.async.wait_group 3;\n" ::: "memory");
}

__global__ __launch_bounds__(THR) void router_pipe_kernel(
    const float4* __restrict__ x4,
    const float*  __restrict__ weights,
    const float4* __restrict__ W4,
    const float*  __restrict__ b,
    float*        __restrict__ out,
    int L, int Hv)
{
    // +1 float4 row padding: row stride 17*4=68 words, 68 mod 32 = 4 ->
    // conflict-free LDS.128 across the 16 row-pairs of a warp.
    __shared__ float4 sx[STG][RPB][PKT + 1];

    const int tid     = threadIdx.x;
    const int rowbase = blockIdx.x * RPB;
    const int row     = rowbase + (tid >> 1);
    const int e       = tid & 1;

    const float4* __restrict__ xblk = x4 + (size_t)rowbase * Hv;
    const float4* __restrict__ wr   = W4 + (size_t)e * Hv;

    const int nstages = Hv / PKT;   // 64 for Hv=1024

    // Issue one stage's cooperative loads: 32 rows x 16 packets = 512 float4,
    // 8 per thread, coalesced (consecutive tid -> consecutive packet).
    auto issue = [&](int s) {
        const int st   = s & (STG - 1);
        const int gpkt = s * PKT;
        #pragma unroll
        for (int k = 0; k < (RPB * PKT) / THR; k++) {
            const int idx = tid + k * THR;
            const int r   = idx >> 4;    // 0..31
            const int p   = idx & 15;    // 0..15
            cp_async16(&sx[st][r][p], &xblk[(size_t)r * Hv + gpkt + p]);
        }
        cp_commit();
    };

    // Prologue: fill 3 stages.
    issue(0); issue(1); issue(2);

    // 4 independent lane accumulators (NEON lanes), ascending packet order.
    float a0 = 0.f, a1 = 0.f, a2 = 0.f, a3 = 0.f;
    const int rloc = tid >> 1;

    #pragma unroll 1
    for (int s = 0; s < nstages; s++) {
        // Keep group accounting uniform: issue a (possibly empty) group.
        if (s + STG - 1 < nstages) issue(s + STG - 1);
        else                       cp_commit();

        cp_wait3();            // stage s complete (4 groups pending -> <=3)
        __syncthreads();       // visible to all threads

        const int st   = s & (STG - 1);
        const int gpkt = s * PKT;
        #pragma unroll
        for (int j = 0; j < PKT; j++) {
            const float4 xv = sx[st][rloc][j];
            const float4 wv = __ldg(&wr[gpkt + j]);
            a0 = fmaf(xv.x, wv.x, a0);
            a1 = fmaf(xv.y, wv.y, a1);
            a2 = fmaf(xv.z, wv.z, a2);
            a3 = fmaf(xv.w, wv.w, a3);
        }
        __syncthreads();       // all consumers done before slot reuse
    }

    // Eigen NEON predux order: (a0+a2) + (a1+a3).
    const float acc = __fadd_rn(__fadd_rn(a0, a2), __fadd_rn(a1, a3));

    // lin_e = dot_e + b_e   (single rounding)
    const float lin = __fadd_rn(acc, __ldg(&b[e]));

    // den = lin0 + lin1 (single rounding). Partner thread is adjacent lane.
    const float other = __shfl_xor_sync(0xffffffffu, lin, 1);
    const float lin0  = (e == 0) ? lin : other;
    const float lin1  = (e == 0) ? other : lin;
    const float den   = __fadd_rn(lin0, lin1);

    // IEEE correctly-rounded fp32 division.
    const float l = __fdiv_rn(lin, den);

    // hs = weights[row // (L/2)][0]; weights is (2,2) row-major.
    const float hs = __ldg(&weights[(row >= (L >> 1)) ? 2 : 0]);

    float rr_self, rr2;
    if (hs >= FT) {
        rr2     = __fdiv_rn(__fsub_rn(1.0f, hs), 1.0f - FT);
        rr_self = (e == 0) ? __fdiv_rn(__fsub_rn(hs, FT), 1.0f - FT) : 0.0f;
    } else {
        rr2     = __fdiv_rn(hs, FT);
        rr_self = (e == 0) ? 0.0f : __fdiv_rn(__fsub_rn(FT, hs), FT);
    }

    // einsum epilogue: out = rr_self + round(rr2 * lin), mul then add.
    out[row * 2 + e] = __fadd_rn(rr_self, __fmul_rn(rr2, l));
}

extern "C" void kernel_launch(void* const* d_in, const int* in_sizes, int n_in,
                              void* d_out, int out_size) {
    const float* x       = (const float*)d_in[0];
    const float* weights = (const float*)d_in[1];
    const float* W       = (const float*)d_in[2];
    const float* b       = (const float*)d_in[3];
    float* out = (float*)d_out;

    const int E  = in_sizes[3];            // 2
    const int H  = in_sizes[2] / E;        // 4096
    const int L  = in_sizes[0] / H;        // 8192
    const int Hv = H / 4;                  // 1024

    const int blocks = L / RPB;            // 256

    router_pipe_kernel<<<blocks, THR>>>((const float4*)x, weights,
                                        (const float4*)W, b, out, L, Hv);
}

// round 10
// speedup vs baseline: 2.1743x; 1.8503x over previous
#include <cuda_runtime.h>

// CustomRouterRouter — reference-rounding-matched (Eigen/NEON gemv realization),
// lane-split across threads + cp.async 4-stage pipeline.
//
// Numerics (LOCKED, rel_err 3.06e-5): per (row,e), 4 fp32 lane accumulators,
// lane j takes k ≡ j (mod 4), fused FMA, ascending k; predux (a0+a2)+(a1+a3);
// single-rounding epilogue (+b, den add, IEEE div, mul-then-add).
//
// Parallelism: the 4 lane chains are independent -> one thread per (row, j),
// handling BOTH e's (x scalar shared by 2 FMAs). 32768 threads / 1024 warps.
// x and the per-stage W slice are staged via cp.async.cg; scalar smem reads
// are conflict-free (bank = 4*rloc + 4p + j covers all 32).

#define FT   0.5f
#define PKT  16            // float4 packets per stage per row
#define STG  4             // pipeline stages
#define RPB  8             // rows per block
#define THR  32            // one warp per block: 8 rows x 4 lanes

__device__ __forceinline__ void cp_async16(void* smem_dst, const void* gmem_src) {
    unsigned saddr = (unsigned)__cvta_generic_to_shared(smem_dst);
    asm volatile("cp.async.cg.shared.global [%0], [%1], 16;\n"
                 :: "r"(saddr), "l"(gmem_src));
}
__device__ __forceinline__ void cp_commit() {
    asm volatile("cp.async.commit_group;\n" ::: "memory");
}
__device__ __forceinline__ void cp_wait3() {
    asm volatile("cp.async.wait_group 3;\n" ::: "memory");
}

__global__ __launch_bounds__(THR) void router_lane_kernel(
    const float4* __restrict__ x4,
    const float*  __restrict__ weights,
    const float4* __restrict__ W4,
    const float*  __restrict__ b,
    float*        __restrict__ out,
    int L, int Hv)
{
    // x: [stage][row][packet], +1 float4 row pad -> bank-conflict-free scalars.
    // w: [stage][e][packet],  +1 float4 pad -> e=1 shifted 4 banks.
    __shared__ float4 sx[STG][RPB][PKT + 1];
    __shared__ float4 sw[STG][2][PKT + 1];

    const int tid     = threadIdx.x;
    const int rloc    = tid >> 2;          // 0..7
    const int j       = tid & 3;           // lane
    const int rowbase = blockIdx.x * RPB;
    const int row     = rowbase + rloc;

    const float4* __restrict__ xblk = x4 + (size_t)rowbase * Hv;

    const int nstages = Hv / PKT;          // 64

    auto issue = [&](int s) {
        const int st   = s & (STG - 1);
        const int gpkt = s * PKT;
        // x: 8 rows x 16 packets = 128 float4, 4 per thread, coalesced.
        #pragma unroll
        for (int k = 0; k < (RPB * PKT) / THR; k++) {
            const int idx = tid + k * THR;
            const int r   = idx >> 4;
            const int p   = idx & 15;
            cp_async16(&sx[st][r][p], &xblk[(size_t)r * Hv + gpkt + p]);
        }
        // W slice: 2 x 16 packets, one per thread.
        {
            const int e = tid >> 4;
            const int p = tid & 15;
            cp_async16(&sw[st][e][p], &W4[(size_t)e * Hv + gpkt + p]);
        }
        cp_commit();
    };

    issue(0); issue(1); issue(2);

    // One lane chain per thread, both e's. Ascending global packet order.
    float acc0 = 0.f, acc1 = 0.f;

    #pragma unroll 1
    for (int s = 0; s < nstages; s++) {
        if (s + STG - 1 < nstages) issue(s + STG - 1);
        else                       cp_commit();

        cp_wait3();
        __syncwarp();

        const int st = s & (STG - 1);
        const float* xf = reinterpret_cast<const float*>(&sx[st][rloc][0]) + j;
        const float* w0 = reinterpret_cast<const float*>(&sw[st][0][0]) + j;
        const float* w1 = reinterpret_cast<const float*>(&sw[st][1][0]) + j;
        #pragma unroll
        for (int p = 0; p < PKT; p++) {
            const float xs = xf[4 * p];
            acc0 = fmaf(xs, w0[4 * p], acc0);
            acc1 = fmaf(xs, w1[4 * p], acc1);
        }
        __syncwarp();
    }

    // Predux across the 4 lane threads, Eigen NEON order: (a0+a2)+(a1+a3).
    float v;
    v = __shfl_xor_sync(0xffffffffu, acc0, 2);
    float t0 = __fadd_rn(acc0, v);
    v = __shfl_xor_sync(0xffffffffu, t0, 1);
    const float A0 = __fadd_rn(t0, v);

    v = __shfl_xor_sync(0xffffffffu, acc1, 2);
    float t1 = __fadd_rn(acc1, v);
    v = __shfl_xor_sync(0xffffffffu, t1, 1);
    const float A1 = __fadd_rn(t1, v);

    // Single-rounding epilogue (all threads compute; lane j==0 writes).
    const float lin0 = __fadd_rn(A0, __ldg(&b[0]));
    const float lin1 = __fadd_rn(A1, __ldg(&b[1]));
    const float den  = __fadd_rn(lin0, lin1);
    const float l0   = __fdiv_rn(lin0, den);
    const float l1   = __fdiv_rn(lin1, den);

    const float hs = __ldg(&weights[(row >= (L >> 1)) ? 2 : 0]);
    float rr0, rr1, rr2;
    if (hs >= FT) {
        rr2 = __fdiv_rn(__fsub_rn(1.0f, hs), 1.0f - FT);
        rr0 = __fdiv_rn(__fsub_rn(hs, FT), 1.0f - FT);
        rr1 = 0.0f;
    } else {
        rr2 = __fdiv_rn(hs, FT);
        rr0 = 0.0f;
        rr1 = __fdiv_rn(__fsub_rn(FT, hs), FT);
    }

    if (j == 0) {
        out[row * 2 + 0] = __fadd_rn(rr0, __fmul_rn(rr2, l0));
        out[row * 2 + 1] = __fadd_rn(rr1, __fmul_rn(rr2, l1));
    }
}

extern "C" void kernel_launch(void* const* d_in, const int* in_sizes, int n_in,
                              void* d_out, int out_size) {
    const float* x       = (const float*)d_in[0];
    const float* weights = (const float*)d_in[1];
    const float* W       = (const float*)d_in[2];
    const float* b       = (const float*)d_in[3];
    float* out = (float*)d_out;

    const int E  = in_sizes[3];            // 2
    const int H  = in_sizes[2] / E;        // 4096
    const int L  = in_sizes[0] / H;        // 8192
    const int Hv = H / 4;                  // 1024

    const int blocks = L / RPB;            // 1024

    router_lane_kernel<<<blocks, THR>>>((const float4*)x, weights,
                                        (const float4*)W, b, out, L, Hv);
}